// round 13
// baseline (speedup 1.0000x reference)
#include <cuda_runtime.h>
#include <math.h>

#define Bc   8
#define Tc   2048
#define Ec   64
#define Hc   8
#define DKc  8
#define FFc  256
#define NTOK (Bc*Tc)

typedef unsigned long long u64;

// ---- packed f32x2 helpers (bit-exact fp32 per lane) ----
__device__ __forceinline__ u64 pack2(float lo, float hi) {
    u64 r; asm("mov.b64 %0,{%1,%2};" : "=l"(r) : "f"(lo), "f"(hi)); return r;
}
__device__ __forceinline__ u64 dup2(float v) {
    u64 r; asm("mov.b64 %0,{%1,%1};" : "=l"(r) : "f"(v)); return r;
}
__device__ __forceinline__ void unpack2(u64 v, float& a, float& b) {
    asm("mov.b64 {%0,%1},%2;" : "=f"(a), "=f"(b) : "l"(v));
}
__device__ __forceinline__ u64 fma2(u64 a, u64 b, u64 c) {
    u64 d; asm("fma.rn.f32x2 %0,%1,%2,%3;" : "=l"(d) : "l"(a), "l"(b), "l"(c)); return d;
}
__device__ __forceinline__ u64 mul2(u64 a, u64 b) {
    u64 d; asm("mul.rn.f32x2 %0,%1,%2;" : "=l"(d) : "l"(a), "l"(b)); return d;
}
__device__ __forceinline__ u64 add2(u64 a, u64 b) {
    u64 d; asm("add.rn.f32x2 %0,%1,%2;" : "=l"(d) : "l"(a), "l"(b)); return d;
}
__device__ __forceinline__ float ex2f(float s) {
    float p; asm("ex2.approx.f32 %0,%1;" : "=f"(p) : "f"(s)); return p;
}

// Scratch (device globals)
__device__ float g_q[Bc*Hc*Tc*DKc];     // [b,h,t,d]
__device__ float g_k[Bc*Hc*Tc*DKc];
__device__ float g_v[Bc*Hc*Tc*DKc];
__device__ float g_attn[NTOK*Ec];       // [n, e], e = h*8+d
__device__ float g_x1[NTOK*Ec];
__device__ float g_h[(size_t)FFc*NTOK]; // f-major [f, n]

// =====================================================================
// K1: qkv (R6). grid (NTOK/128, 3), 256 threads, tile 8tok x 4out.
// =====================================================================
__global__ __launch_bounds__(256) void qkv_kernel(
    const float* __restrict__ x,
    const float* __restrict__ Wq, const float* __restrict__ bq,
    const float* __restrict__ Wk, const float* __restrict__ bk,
    const float* __restrict__ Wv, const float* __restrict__ bv,
    const float* __restrict__ theta_p)
{
    extern __shared__ float sm[];
    float* xT = sm;                 // [64][132] = 8448
    float* wT = sm + 8448;          // [64][68]  = 4352
    float* sb = wT + 4352;          // 64
    int tid = threadIdx.x;
    int m = blockIdx.y;

    const float* W = (m == 0) ? Wq : (m == 1) ? Wk : Wv;
    const float* bias = (m == 0) ? bq : (m == 1) ? bk : bv;
    float* gout = (m == 0) ? g_q : (m == 1) ? g_k : g_v;

    for (int i = tid; i < 4096; i += 256) {
        int o = i >> 6, k = i & 63;
        wT[k*68+o] = W[i];
    }
    if (tid < 64) sb[tid] = bias[tid];

    int n0 = blockIdx.x * 128;
    const float4* xsrc = reinterpret_cast<const float4*>(x + (size_t)n0 * Ec);
    for (int i = tid; i < 2048; i += 256) {
        int r = i >> 4, eg = i & 15;
        float4 v = xsrc[i];
        xT[(eg*4+0)*132 + r] = v.x;
        xT[(eg*4+1)*132 + r] = v.y;
        xT[(eg*4+2)*132 + r] = v.z;
        xT[(eg*4+3)*132 + r] = v.w;
    }
    __syncthreads();

    float theta = theta_p[0];
    int tokg = tid & 15, outg = tid >> 4;
    int b = n0 >> 11;
    int tt0 = (n0 & 2047) + tokg * 8;
    int o0 = outg * 4, h = o0 >> 3, d0 = o0 & 7;

    u64 acc[4][4];
#pragma unroll
    for (int a = 0; a < 4; a++)
#pragma unroll
        for (int j = 0; j < 4; j++) acc[a][j] = 0;

#pragma unroll 4
    for (int k = 0; k < 64; k++) {
        const ulonglong2* xr = reinterpret_cast<const ulonglong2*>(xT + k*132 + tokg*8);
        ulonglong2 xa = xr[0], xb = xr[1];
        float4 wv = *reinterpret_cast<const float4*>(wT + k*68 + o0);
        u64 w0 = dup2(wv.x), w1 = dup2(wv.y), w2 = dup2(wv.z), w3 = dup2(wv.w);
        acc[0][0]=fma2(xa.x,w0,acc[0][0]); acc[0][1]=fma2(xa.x,w1,acc[0][1]);
        acc[0][2]=fma2(xa.x,w2,acc[0][2]); acc[0][3]=fma2(xa.x,w3,acc[0][3]);
        acc[1][0]=fma2(xa.y,w0,acc[1][0]); acc[1][1]=fma2(xa.y,w1,acc[1][1]);
        acc[1][2]=fma2(xa.y,w2,acc[1][2]); acc[1][3]=fma2(xa.y,w3,acc[1][3]);
        acc[2][0]=fma2(xb.x,w0,acc[2][0]); acc[2][1]=fma2(xb.x,w1,acc[2][1]);
        acc[2][2]=fma2(xb.x,w2,acc[2][2]); acc[2][3]=fma2(xb.x,w3,acc[2][3]);
        acc[3][0]=fma2(xb.y,w0,acc[3][0]); acc[3][1]=fma2(xb.y,w1,acc[3][1]);
        acc[3][2]=fma2(xb.y,w2,acc[3][2]); acc[3][3]=fma2(xb.y,w3,acc[3][3]);
    }
    float bb0 = sb[o0+0]+theta, bb1 = sb[o0+1]+theta,
          bb2 = sb[o0+2]+theta, bb3 = sb[o0+3]+theta;
    size_t gbase = ((size_t)b*Hc + h) * (Tc*DKc) + d0;
#pragma unroll
    for (int tp = 0; tp < 4; tp++) {
        float v00,v10, v01,v11, v02,v12, v03,v13;
        unpack2(acc[tp][0], v00, v10);
        unpack2(acc[tp][1], v01, v11);
        unpack2(acc[tp][2], v02, v12);
        unpack2(acc[tp][3], v03, v13);
        int t0 = tt0 + tp*2;
        float4 r0 = make_float4(__cosf(v00+bb0), __cosf(v01+bb1), __cosf(v02+bb2), __cosf(v03+bb3));
        float4 r1 = make_float4(__cosf(v10+bb0), __cosf(v11+bb1), __cosf(v12+bb2), __cosf(v13+bb3));
        *reinterpret_cast<float4*>(gout + gbase + (size_t)t0*8)     = r0;
        *reinterpret_cast<float4*>(gout + gbase + (size_t)(t0+1)*8) = r1;
    }
}

// =====================================================================
// K2: attention. R6 shell (512 thr, 2 rows/thread, grid (64,2)) with
// KEY-PAIRED V: PV uses packed (p0,p1) directly -> no dup2 in the loop.
// Per (row,2keys): 19 fma-class ops (was 21).
// =====================================================================
__global__ __launch_bounds__(512) void attn_kernel()
{
    extern __shared__ float sm[];
    u64* K2p = reinterpret_cast<u64*>(sm);            // [1024][8]  64KB
    u64* V2p = reinterpret_cast<u64*>(sm + 16384);    // [1024][8]  64KB

    int bh  = blockIdx.x;
    int qt  = blockIdx.y;   // 0..1
    int tid = threadIdx.x;

    const float* gk = g_k + (size_t)bh * (Tc*DKc);
    const float* gv = g_v + (size_t)bh * (Tc*DKc);
#pragma unroll
    for (int i = tid; i < 8192; i += 512) {
        int j2 = i >> 3, d = i & 7;
        K2p[i] = pack2(gk[j2*16 + d], gk[j2*16 + 8 + d]);
        V2p[i] = pack2(gv[j2*16 + d], gv[j2*16 + 8 + d]);
    }
    __syncthreads();

    int t0 = qt * 1024 + tid;
    int t1 = t0 + 512;
    const float QS = 0.35355339059327f * 1.4426950408889634f;  // 1/sqrt(8)*log2(e)
    const float* qp0 = g_q + (size_t)bh * (Tc*DKc) + t0 * DKc;
    const float* qp1 = g_q + (size_t)bh * (Tc*DKc) + t1 * DKc;
    u64 qa[8], qb[8];
#pragma unroll
    for (int d = 0; d < 8; d++) { qa[d] = dup2(qp0[d]*QS); qb[d] = dup2(qp1[d]*QS); }

    u64 la = 0, lb = 0;
    u64 aA[8], aB[8];
#pragma unroll
    for (int d = 0; d < 8; d++) { aA[d] = 0; aB[d] = 0; }

    const ulonglong2* kp = reinterpret_cast<const ulonglong2*>(K2p);
    const ulonglong2* vp = reinterpret_cast<const ulonglong2*>(V2p);

#pragma unroll 2
    for (int j2 = 0; j2 < 1024; j2++) {
        ulonglong2 kA = kp[0], kB = kp[1], kC = kp[2], kD = kp[3]; kp += 4;
        u64 sA = mul2(qa[0], kA.x);
        u64 sB = mul2(qb[0], kA.x);
        sA = fma2(qa[1], kA.y, sA);  sB = fma2(qb[1], kA.y, sB);
        sA = fma2(qa[2], kB.x, sA);  sB = fma2(qb[2], kB.x, sB);
        sA = fma2(qa[3], kB.y, sA);  sB = fma2(qb[3], kB.y, sB);
        sA = fma2(qa[4], kC.x, sA);  sB = fma2(qb[4], kC.x, sB);
        sA = fma2(qa[5], kC.y, sA);  sB = fma2(qb[5], kC.y, sB);
        sA = fma2(qa[6], kD.x, sA);  sB = fma2(qb[6], kD.x, sB);
        sA = fma2(qa[7], kD.y, sA);  sB = fma2(qb[7], kD.y, sB);
        float sa0, sa1, sb0, sb1;
        unpack2(sA, sa0, sa1);
        unpack2(sB, sb0, sb1);
        u64 pA = pack2(ex2f(sa0), ex2f(sa1));
        u64 pB = pack2(ex2f(sb0), ex2f(sb1));
        la = add2(la, pA);
        lb = add2(lb, pB);
        ulonglong2 vA = vp[0], vB = vp[1], vC = vp[2], vD = vp[3]; vp += 4;
        aA[0] = fma2(pA, vA.x, aA[0]);  aB[0] = fma2(pB, vA.x, aB[0]);
        aA[1] = fma2(pA, vA.y, aA[1]);  aB[1] = fma2(pB, vA.y, aB[1]);
        aA[2] = fma2(pA, vB.x, aA[2]);  aB[2] = fma2(pB, vB.x, aB[2]);
        aA[3] = fma2(pA, vB.y, aA[3]);  aB[3] = fma2(pB, vB.y, aB[3]);
        aA[4] = fma2(pA, vC.x, aA[4]);  aB[4] = fma2(pB, vC.x, aB[4]);
        aA[5] = fma2(pA, vC.y, aA[5]);  aB[5] = fma2(pB, vC.y, aB[5]);
        aA[6] = fma2(pA, vD.x, aA[6]);  aB[6] = fma2(pB, vD.x, aB[6]);
        aA[7] = fma2(pA, vD.y, aA[7]);  aB[7] = fma2(pB, vD.y, aB[7]);
    }

    int b = bh >> 3, h = bh & 7;
    {
        float llo, lhi; unpack2(la, llo, lhi);
        float inv = 1.0f / (llo + lhi);
        float o[8];
#pragma unroll
        for (int d = 0; d < 8; d++) { float lo, hi; unpack2(aA[d], lo, hi); o[d] = (lo + hi) * inv; }
        float* op = g_attn + ((size_t)(b*Tc + t0)) * Ec + h * DKc;
        reinterpret_cast<float4*>(op)[0] = make_float4(o[0], o[1], o[2], o[3]);
        reinterpret_cast<float4*>(op)[1] = make_float4(o[4], o[5], o[6], o[7]);
    }
    {
        float llo, lhi; unpack2(lb, llo, lhi);
        float inv = 1.0f / (llo + lhi);
        float o[8];
#pragma unroll
        for (int d = 0; d < 8; d++) { float lo, hi; unpack2(aB[d], lo, hi); o[d] = (lo + hi) * inv; }
        float* op = g_attn + ((size_t)(b*Tc + t1)) * Ec + h * DKc;
        reinterpret_cast<float4*>(op)[0] = make_float4(o[0], o[1], o[2], o[3]);
        reinterpret_cast<float4*>(op)[1] = make_float4(o[4], o[5], o[6], o[7]);
    }
}

// =====================================================================
// K3: oproj + LN (R6 shell: 128-token blocks, 256 threads).
// =====================================================================
__global__ __launch_bounds__(256) void oproj_kernel(
    const float* __restrict__ x, const float* __restrict__ Wo,
    const float* __restrict__ bo, const float* __restrict__ g1,
    const float* __restrict__ be1)
{
    extern __shared__ float sm[];
    float* xT   = sm;             // [64][132] = 8448
    float* wT   = sm + 8448;      // [64][68]  = 4352
    float* sbo  = wT + 4352;      // 64
    float* sg   = sbo + 64;       // 64
    float* sbe  = sg + 64;        // 64
    float* red1 = sbe + 64;       // 128*17 = 2176
    float* red2 = red1 + 2176;    // 2176
    float* mS   = red2 + 2176;    // 128
    float* rsS  = mS + 128;       // 128
    int tid = threadIdx.x;

    for (int i = tid; i < 4096; i += 256) {
        int o = i >> 6, k = i & 63;
        wT[k*68+o] = Wo[i];
    }
    if (tid < 64) { sbo[tid] = bo[tid]; sg[tid] = g1[tid]; sbe[tid] = be1[tid]; }

    int n0 = blockIdx.x * 128;
    const float4* asrc = reinterpret_cast<const float4*>(g_attn + (size_t)n0 * Ec);
    for (int i = tid; i < 2048; i += 256) {
        int r = i >> 4, eg = i & 15;
        float4 v = asrc[i];
        xT[(eg*4+0)*132 + r] = v.x;
        xT[(eg*4+1)*132 + r] = v.y;
        xT[(eg*4+2)*132 + r] = v.z;
        xT[(eg*4+3)*132 + r] = v.w;
    }
    __syncthreads();

    int tokg = tid & 15, outg = tid >> 4;
    int o0 = outg * 4;

    u64 acc[4][4];
#pragma unroll
    for (int a = 0; a < 4; a++)
#pragma unroll
        for (int j = 0; j < 4; j++) acc[a][j] = 0;

#pragma unroll 4
    for (int k = 0; k < 64; k++) {
        const ulonglong2* xr = reinterpret_cast<const ulonglong2*>(xT + k*132 + tokg*8);
        ulonglong2 xa = xr[0], xb = xr[1];
        float4 wv = *reinterpret_cast<const float4*>(wT + k*68 + o0);
        u64 w0 = dup2(wv.x), w1 = dup2(wv.y), w2 = dup2(wv.z), w3 = dup2(wv.w);
        acc[0][0]=fma2(xa.x,w0,acc[0][0]); acc[0][1]=fma2(xa.x,w1,acc[0][1]);
        acc[0][2]=fma2(xa.x,w2,acc[0][2]); acc[0][3]=fma2(xa.x,w3,acc[0][3]);
        acc[1][0]=fma2(xa.y,w0,acc[1][0]); acc[1][1]=fma2(xa.y,w1,acc[1][1]);
        acc[1][2]=fma2(xa.y,w2,acc[1][2]); acc[1][3]=fma2(xa.y,w3,acc[1][3]);
        acc[2][0]=fma2(xb.x,w0,acc[2][0]); acc[2][1]=fma2(xb.x,w1,acc[2][1]);
        acc[2][2]=fma2(xb.x,w2,acc[2][2]); acc[2][3]=fma2(xb.x,w3,acc[2][3]);
        acc[3][0]=fma2(xb.y,w0,acc[3][0]); acc[3][1]=fma2(xb.y,w1,acc[3][1]);
        acc[3][2]=fma2(xb.y,w2,acc[3][2]); acc[3][3]=fma2(xb.y,w3,acc[3][3]);
    }

    float bb0 = sbo[o0+0], bb1 = sbo[o0+1], bb2 = sbo[o0+2], bb3 = sbo[o0+3];
    float y[8][4];
#pragma unroll
    for (int tp = 0; tp < 4; tp++) {
        int lt = tokg*8 + tp*2;
        float4 r0 = *reinterpret_cast<const float4*>(x + (size_t)(n0+lt)   * Ec + o0);
        float4 r1 = *reinterpret_cast<const float4*>(x + (size_t)(n0+lt+1) * Ec + o0);
        float v0,v1;
        unpack2(acc[tp][0], v0, v1); y[tp*2][0] = v0 + r0.x + bb0; y[tp*2+1][0] = v1 + r1.x + bb0;
        unpack2(acc[tp][1], v0, v1); y[tp*2][1] = v0 + r0.y + bb1; y[tp*2+1][1] = v1 + r1.y + bb1;
        unpack2(acc[tp][2], v0, v1); y[tp*2][2] = v0 + r0.z + bb2; y[tp*2+1][2] = v1 + r1.z + bb2;
        unpack2(acc[tp][3], v0, v1); y[tp*2][3] = v0 + r0.w + bb3; y[tp*2+1][3] = v1 + r1.w + bb3;
    }
#pragma unroll
    for (int i = 0; i < 8; i++) {
        int lt = tokg*8 + i;
        float s1 = y[i][0]+y[i][1]+y[i][2]+y[i][3];
        float s2 = y[i][0]*y[i][0]+y[i][1]*y[i][1]+y[i][2]*y[i][2]+y[i][3]*y[i][3];
        red1[lt*17 + outg] = s1;
        red2[lt*17 + outg] = s2;
    }
    __syncthreads();
    if (tid < 128) {
        float s1 = 0.f, s2 = 0.f;
#pragma unroll
        for (int o = 0; o < 16; o++) { s1 += red1[tid*17+o]; s2 += red2[tid*17+o]; }
        float m = s1 * (1.f/64.f);
        float var = s2 * (1.f/64.f) - m*m;
        mS[tid] = m;
        rsS[tid] = rsqrtf(var + 1e-5f);
    }
    __syncthreads();

    float gg0 = sg[o0+0], gg1 = sg[o0+1], gg2 = sg[o0+2], gg3 = sg[o0+3];
    float ee0 = sbe[o0+0], ee1 = sbe[o0+1], ee2 = sbe[o0+2], ee3 = sbe[o0+3];
#pragma unroll
    for (int i = 0; i < 8; i++) {
        int lt = tokg*8 + i;
        float m = mS[lt], rs = rsS[lt];
        float4 v;
        v.x = (y[i][0]-m)*rs*gg0 + ee0;
        v.y = (y[i][1]-m)*rs*gg1 + ee1;
        v.z = (y[i][2]-m)*rs*gg2 + ee2;
        v.w = (y[i][3]-m)*rs*gg3 + ee3;
        *reinterpret_cast<float4*>(g_x1 + (size_t)(n0+lt) * Ec + o0) = v;
    }
}

// =====================================================================
// K4a: ffn_h (R7 — measured 27.4us). grid (NTOK/128, 4), 128 threads.
// =====================================================================
__global__ __launch_bounds__(128) void ffn_h_kernel(
    const float* __restrict__ W1, const float* __restrict__ b1,
    const float* __restrict__ theta_p)
{
    extern __shared__ float sm[];
    float* xT  = sm;             // [64][132] = 8448
    float* w1T = sm + 8448;      // [64][68]  = 4352
    float* sb1 = w1T + 4352;     // 64
    int tid = threadIdx.x;
    int fbase = blockIdx.y * 64;

    for (int i = tid; i < 4096; i += 128) {
        int fl = i >> 6, k = i & 63;
        w1T[k*68 + fl] = W1[(fbase + fl)*64 + k];
    }
    if (tid < 64) sb1[tid] = b1[fbase + tid];

    float ct = __cosf(theta_p[0]);
    int n0 = blockIdx.x * 128;
    const float4* xsrc = reinterpret_cast<const float4*>(g_x1 + (size_t)n0 * Ec);
    for (int i = tid; i < 2048; i += 128) {
        int r = i >> 4, eg = i & 15;
        float4 v = xsrc[i];
        xT[(eg*4+0)*132 + r] = __cosf(v.x)*ct;
        xT[(eg*4+1)*132 + r] = __cosf(v.y)*ct;
        xT[(eg*4+2)*132 + r] = __cosf(v.z)*ct;
        xT[(eg*4+3)*132 + r] = __cosf(v.w)*ct;
    }
    __syncthreads();

    int tokg = tid & 15, outg = tid >> 4;
    int o0 = outg * 8;

    u64 acc[4][8];
#pragma unroll
    for (int a = 0; a < 4; a++)
#pragma unroll
        for (int j = 0; j < 8; j++) acc[a][j] = 0;

#pragma unroll 2
    for (int k = 0; k < 64; k++) {
        const ulonglong2* xr = reinterpret_cast<const ulonglong2*>(xT + k*132 + tokg*8);
        ulonglong2 xa = xr[0], xb = xr[1];
        float4 wva = *reinterpret_cast<const float4*>(w1T + k*68 + o0);
        float4 wvb = *reinterpret_cast<const float4*>(w1T + k*68 + o0 + 4);
        u64 w[8];
        w[0]=dup2(wva.x); w[1]=dup2(wva.y); w[2]=dup2(wva.z); w[3]=dup2(wva.w);
        w[4]=dup2(wvb.x); w[5]=dup2(wvb.y); w[6]=dup2(wvb.z); w[7]=dup2(wvb.w);
#pragma unroll
        for (int j = 0; j < 8; j++) {
            acc[0][j] = fma2(xa.x, w[j], acc[0][j]);
            acc[1][j] = fma2(xa.y, w[j], acc[1][j]);
            acc[2][j] = fma2(xb.x, w[j], acc[2][j]);
            acc[3][j] = fma2(xb.y, w[j], acc[3][j]);
        }
    }
#pragma unroll
    for (int j = 0; j < 8; j++) {
        int f = fbase + o0 + j;
        float bb = sb1[o0 + j];
        float a0,a1,b0,b1,c0,c1,d0,d1;
        unpack2(acc[0][j], a0, a1);
        unpack2(acc[1][j], b0, b1);
        unpack2(acc[2][j], c0, c1);
        unpack2(acc[3][j], d0, d1);
        float4 h0 = make_float4(fmaxf(a0+bb,0.f), fmaxf(a1+bb,0.f),
                                fmaxf(b0+bb,0.f), fmaxf(b1+bb,0.f));
        float4 h1 = make_float4(fmaxf(c0+bb,0.f), fmaxf(c1+bb,0.f),
                                fmaxf(d0+bb,0.f), fmaxf(d1+bb,0.f));
        float* hp = g_h + (size_t)f * NTOK + n0 + tokg*8;
        reinterpret_cast<float4*>(hp)[0] = h0;
        reinterpret_cast<float4*>(hp)[1] = h1;
    }
}

// =====================================================================
// K4b: ffn_out (R6 shell: 128-token blocks, 256 threads).
// =====================================================================
__global__ __launch_bounds__(256) void ffn_out_kernel(
    const float* __restrict__ W2, const float* __restrict__ b2,
    const float* __restrict__ g2, const float* __restrict__ be2,
    float* __restrict__ out)
{
    extern __shared__ float sm[];
    float* w2T  = sm;             // [256][68] = 17408
    float* sb2  = sm + 17408;     // 64
    float* sg   = sb2 + 64;
    float* sbe  = sg + 64;
    float* red1 = sbe + 64;       // 2176
    float* red2 = red1 + 2176;
    float* mS   = red2 + 2176;    // 128
    float* rsS  = mS + 128;
    int tid = threadIdx.x;

    for (int i = tid; i < Ec*FFc; i += 256) {
        int e = i >> 8, f = i & 255;
        w2T[f*68 + e] = W2[i];
    }
    if (tid < 64) { sb2[tid] = b2[tid]; sg[tid] = g2[tid]; sbe[tid] = be2[tid]; }
    __syncthreads();

    int n0 = blockIdx.x * 128;
    int tokg = tid & 15, outg = tid >> 4;
    int o0 = outg * 4;

    u64 acc[4][4];
#pragma unroll
    for (int a = 0; a < 4; a++)
#pragma unroll
        for (int j = 0; j < 4; j++) acc[a][j] = 0;

#pragma unroll 4
    for (int k = 0; k < 256; k++) {
        const ulonglong2* hp = reinterpret_cast<const ulonglong2*>(g_h + (size_t)k * NTOK + n0 + tokg*8);
        ulonglong2 xa = hp[0], xb = hp[1];
        float4 wv = *reinterpret_cast<const float4*>(w2T + k*68 + o0);
        u64 w0 = dup2(wv.x), w1 = dup2(wv.y), w2_ = dup2(wv.z), w3 = dup2(wv.w);
        acc[0][0]=fma2(xa.x,w0,acc[0][0]); acc[0][1]=fma2(xa.x,w1,acc[0][1]);
        acc[0][2]=fma2(xa.x,w2_,acc[0][2]); acc[0][3]=fma2(xa.x,w3,acc[0][3]);
        acc[1][0]=fma2(xa.y,w0,acc[1][0]); acc[1][1]=fma2(xa.y,w1,acc[1][1]);
        acc[1][2]=fma2(xa.y,w2_,acc[1][2]); acc[1][3]=fma2(xa.y,w3,acc[1][3]);
        acc[2][0]=fma2(xb.x,w0,acc[2][0]); acc[2][1]=fma2(xb.x,w1,acc[2][1]);
        acc[2][2]=fma2(xb.x,w2_,acc[2][2]); acc[2][3]=fma2(xb.x,w3,acc[2][3]);
        acc[3][0]=fma2(xb.y,w0,acc[3][0]); acc[3][1]=fma2(xb.y,w1,acc[3][1]);
        acc[3][2]=fma2(xb.y,w2_,acc[3][2]); acc[3][3]=fma2(xb.y,w3,acc[3][3]);
    }

    float bb0 = sb2[o0+0], bb1 = sb2[o0+1], bb2v = sb2[o0+2], bb3 = sb2[o0+3];
    float y[8][4];
#pragma unroll
    for (int tp = 0; tp < 4; tp++) {
        int lt = tokg*8 + tp*2;
        float4 r0 = *reinterpret_cast<const float4*>(g_x1 + (size_t)(n0+lt)   * Ec + o0);
        float4 r1 = *reinterpret_cast<const float4*>(g_x1 + (size_t)(n0+lt+1) * Ec + o0);
        float v0,v1;
        unpack2(acc[tp][0], v0, v1); y[tp*2][0] = v0 + r0.x + bb0; y[tp*2+1][0] = v1 + r1.x + bb0;
        unpack2(acc[tp][1], v0, v1); y[tp*2][1] = v0 + r0.y + bb1; y[tp*2+1][1] = v1 + r1.y + bb1;
        unpack2(acc[tp][2], v0, v1); y[tp*2][2] = v0 + r0.z + bb2v; y[tp*2+1][2] = v1 + r1.z + bb2v;
        unpack2(acc[tp][3], v0, v1); y[tp*2][3] = v0 + r0.w + bb3; y[tp*2+1][3] = v1 + r1.w + bb3;
    }
#pragma unroll
    for (int i = 0; i < 8; i++) {
        int lt = tokg*8 + i;
        float s1 = y[i][0]+y[i][1]+y[i][2]+y[i][3];
        float s2 = y[i][0]*y[i][0]+y[i][1]*y[i][1]+y[i][2]*y[i][2]+y[i][3]*y[i][3];
        red1[lt*17 + outg] = s1;
        red2[lt*17 + outg] = s2;
    }
    __syncthreads();
    if (tid < 128) {
        float s1 = 0.f, s2 = 0.f;
#pragma unroll
        for (int o = 0; o < 16; o++) { s1 += red1[tid*17+o]; s2 += red2[tid*17+o]; }
        float m = s1 * (1.f/64.f);
        float var = s2 * (1.f/64.f) - m*m;
        mS[tid] = m;
        rsS[tid] = rsqrtf(var + 1e-5f);
    }
    __syncthreads();

    float gg0 = sg[o0+0], gg1 = sg[o0+1], gg2 = sg[o0+2], gg3 = sg[o0+3];
    float ee0 = sbe[o0+0], ee1 = sbe[o0+1], ee2 = sbe[o0+2], ee3 = sbe[o0+3];
#pragma unroll
    for (int i = 0; i < 8; i++) {
        int lt = tokg*8 + i;
        float m = mS[lt], rs = rsS[lt];
        float4 v;
        v.x = (y[i][0]-m)*rs*gg0 + ee0;
        v.y = (y[i][1]-m)*rs*gg1 + ee1;
        v.z = (y[i][2]-m)*rs*gg2 + ee2;
        v.w = (y[i][3]-m)*rs*gg3 + ee3;
        *reinterpret_cast<float4*>(out + (size_t)(n0+lt) * Ec + o0) = v;
    }
}

// ---------------------------------------------------------------------------
extern "C" void kernel_launch(void* const* d_in, const int* in_sizes, int n_in,
                              void* d_out, int out_size)
{
    const float* x     = (const float*)d_in[0];
    const float* Wq    = (const float*)d_in[1];
    const float* bq    = (const float*)d_in[2];
    const float* Wk    = (const float*)d_in[3];
    const float* bk    = (const float*)d_in[4];
    const float* Wv    = (const float*)d_in[5];
    const float* bv    = (const float*)d_in[6];
    const float* Wo    = (const float*)d_in[7];
    const float* bo    = (const float*)d_in[8];
    const float* th_a  = (const float*)d_in[9];
    const float* th_f  = (const float*)d_in[10];
    const float* W1    = (const float*)d_in[11];
    const float* b1    = (const float*)d_in[12];
    const float* W2    = (const float*)d_in[13];
    const float* b2    = (const float*)d_in[14];
    const float* g1    = (const float*)d_in[15];
    const float* be1   = (const float*)d_in[16];
    const float* g2    = (const float*)d_in[17];
    const float* be2   = (const float*)d_in[18];
    float* out = (float*)d_out;

    const size_t SM1 = (8448 + 4352 + 64) * sizeof(float);                   // 51,456
    const size_t SM2 = 131072;                                               // K-paired + V-paired
    const size_t SM3 = (8448 + 4352 + 192 + 2*2176 + 256) * sizeof(float);   // 70,400
    const size_t SM4a = (8448 + 4352 + 64) * sizeof(float);                  // 51,456
    const size_t SM4b = (17408 + 192 + 2*2176 + 256) * sizeof(float);        // 88,832

    cudaFuncSetAttribute(qkv_kernel,    cudaFuncAttributeMaxDynamicSharedMemorySize, (int)SM1);
    cudaFuncSetAttribute(attn_kernel,   cudaFuncAttributeMaxDynamicSharedMemorySize, (int)SM2);
    cudaFuncSetAttribute(oproj_kernel,  cudaFuncAttributeMaxDynamicSharedMemorySize, (int)SM3);
    cudaFuncSetAttribute(ffn_h_kernel,  cudaFuncAttributeMaxDynamicSharedMemorySize, (int)SM4a);
    cudaFuncSetAttribute(ffn_out_kernel,cudaFuncAttributeMaxDynamicSharedMemorySize, (int)SM4b);

    qkv_kernel<<<dim3(NTOK/128, 3), 256, SM1>>>(x, Wq, bq, Wk, bk, Wv, bv, th_a);
    attn_kernel<<<dim3(Bc*Hc, 2), 512, SM2>>>();
    oproj_kernel<<<NTOK/128, 256, SM3>>>(x, Wo, bo, g1, be1);
    ffn_h_kernel<<<dim3(NTOK/128, 4), 128, SM4a>>>(W1, b1, th_f);
    ffn_out_kernel<<<NTOK/128, 256, SM4b>>>(W2, b2, g2, be2, out);
}

// round 15
// speedup vs baseline: 1.1607x; 1.1607x over previous
#include <cuda_runtime.h>
#include <math.h>

#define Bc   8
#define Tc   2048
#define Ec   64
#define Hc   8
#define DKc  8
#define FFc  256
#define NTOK (Bc*Tc)

typedef unsigned long long u64;

// ---- packed f32x2 helpers (bit-exact fp32 per lane) ----
__device__ __forceinline__ u64 pack2(float lo, float hi) {
    u64 r; asm("mov.b64 %0,{%1,%2};" : "=l"(r) : "f"(lo), "f"(hi)); return r;
}
__device__ __forceinline__ u64 dup2(float v) {
    u64 r; asm("mov.b64 %0,{%1,%1};" : "=l"(r) : "f"(v)); return r;
}
__device__ __forceinline__ void unpack2(u64 v, float& a, float& b) {
    asm("mov.b64 {%0,%1},%2;" : "=f"(a), "=f"(b) : "l"(v));
}
__device__ __forceinline__ u64 fma2(u64 a, u64 b, u64 c) {
    u64 d; asm("fma.rn.f32x2 %0,%1,%2,%3;" : "=l"(d) : "l"(a), "l"(b), "l"(c)); return d;
}
__device__ __forceinline__ u64 mul2(u64 a, u64 b) {
    u64 d; asm("mul.rn.f32x2 %0,%1,%2;" : "=l"(d) : "l"(a), "l"(b)); return d;
}
__device__ __forceinline__ u64 add2(u64 a, u64 b) {
    u64 d; asm("add.rn.f32x2 %0,%1,%2;" : "=l"(d) : "l"(a), "l"(b)); return d;
}
__device__ __forceinline__ float ex2f(float s) {
    float p; asm("ex2.approx.f32 %0,%1;" : "=f"(p) : "f"(s)); return p;
}

// Scratch (device globals)
__device__ float g_q[Bc*Hc*Tc*DKc];     // [b,h,t,d]
__device__ float g_k[Bc*Hc*Tc*DKc];
__device__ float g_v[Bc*Hc*Tc*DKc];
__device__ float g_attn[NTOK*Ec];       // [n, e], e = h*8+d

// =====================================================================
// K1: qkv (R6 verbatim). grid (NTOK/128, 3), 256 threads.
// =====================================================================
__global__ __launch_bounds__(256) void qkv_kernel(
    const float* __restrict__ x,
    const float* __restrict__ Wq, const float* __restrict__ bq,
    const float* __restrict__ Wk, const float* __restrict__ bk,
    const float* __restrict__ Wv, const float* __restrict__ bv,
    const float* __restrict__ theta_p)
{
    extern __shared__ float sm[];
    float* xT = sm;                 // [64][132] = 8448
    float* wT = sm + 8448;          // [64][68]  = 4352
    float* sb = wT + 4352;          // 64
    int tid = threadIdx.x;
    int m = blockIdx.y;

    const float* W = (m == 0) ? Wq : (m == 1) ? Wk : Wv;
    const float* bias = (m == 0) ? bq : (m == 1) ? bk : bv;
    float* gout = (m == 0) ? g_q : (m == 1) ? g_k : g_v;

    for (int i = tid; i < 4096; i += 256) {
        int o = i >> 6, k = i & 63;
        wT[k*68+o] = W[i];
    }
    if (tid < 64) sb[tid] = bias[tid];

    int n0 = blockIdx.x * 128;
    const float4* xsrc = reinterpret_cast<const float4*>(x + (size_t)n0 * Ec);
    for (int i = tid; i < 2048; i += 256) {
        int r = i >> 4, eg = i & 15;
        float4 v = xsrc[i];
        xT[(eg*4+0)*132 + r] = v.x;
        xT[(eg*4+1)*132 + r] = v.y;
        xT[(eg*4+2)*132 + r] = v.z;
        xT[(eg*4+3)*132 + r] = v.w;
    }
    __syncthreads();

    float theta = theta_p[0];
    int tokg = tid & 15, outg = tid >> 4;
    int b = n0 >> 11;
    int tt0 = (n0 & 2047) + tokg * 8;
    int o0 = outg * 4, h = o0 >> 3, d0 = o0 & 7;

    u64 acc[4][4];
#pragma unroll
    for (int a = 0; a < 4; a++)
#pragma unroll
        for (int j = 0; j < 4; j++) acc[a][j] = 0;

#pragma unroll 4
    for (int k = 0; k < 64; k++) {
        const ulonglong2* xr = reinterpret_cast<const ulonglong2*>(xT + k*132 + tokg*8);
        ulonglong2 xa = xr[0], xb = xr[1];
        float4 wv = *reinterpret_cast<const float4*>(wT + k*68 + o0);
        u64 w0 = dup2(wv.x), w1 = dup2(wv.y), w2 = dup2(wv.z), w3 = dup2(wv.w);
        acc[0][0]=fma2(xa.x,w0,acc[0][0]); acc[0][1]=fma2(xa.x,w1,acc[0][1]);
        acc[0][2]=fma2(xa.x,w2,acc[0][2]); acc[0][3]=fma2(xa.x,w3,acc[0][3]);
        acc[1][0]=fma2(xa.y,w0,acc[1][0]); acc[1][1]=fma2(xa.y,w1,acc[1][1]);
        acc[1][2]=fma2(xa.y,w2,acc[1][2]); acc[1][3]=fma2(xa.y,w3,acc[1][3]);
        acc[2][0]=fma2(xb.x,w0,acc[2][0]); acc[2][1]=fma2(xb.x,w1,acc[2][1]);
        acc[2][2]=fma2(xb.x,w2,acc[2][2]); acc[2][3]=fma2(xb.x,w3,acc[2][3]);
        acc[3][0]=fma2(xb.y,w0,acc[3][0]); acc[3][1]=fma2(xb.y,w1,acc[3][1]);
        acc[3][2]=fma2(xb.y,w2,acc[3][2]); acc[3][3]=fma2(xb.y,w3,acc[3][3]);
    }
    float bb0 = sb[o0+0]+theta, bb1 = sb[o0+1]+theta,
          bb2 = sb[o0+2]+theta, bb3 = sb[o0+3]+theta;
    size_t gbase = ((size_t)b*Hc + h) * (Tc*DKc) + d0;
#pragma unroll
    for (int tp = 0; tp < 4; tp++) {
        float v00,v10, v01,v11, v02,v12, v03,v13;
        unpack2(acc[tp][0], v00, v10);
        unpack2(acc[tp][1], v01, v11);
        unpack2(acc[tp][2], v02, v12);
        unpack2(acc[tp][3], v03, v13);
        int t0 = tt0 + tp*2;
        float4 r0 = make_float4(__cosf(v00+bb0), __cosf(v01+bb1), __cosf(v02+bb2), __cosf(v03+bb3));
        float4 r1 = make_float4(__cosf(v10+bb0), __cosf(v11+bb1), __cosf(v12+bb2), __cosf(v13+bb3));
        *reinterpret_cast<float4*>(gout + gbase + (size_t)t0*8)     = r0;
        *reinterpret_cast<float4*>(gout + gbase + (size_t)(t0+1)*8) = r1;
    }
}

// =====================================================================
// K2: attention (R6 verbatim — best measured). 512 threads, 2 rows/thread,
// grid (64,2), K-paired + V dim-paired smem 128KB.
// =====================================================================
__global__ __launch_bounds__(512) void attn_kernel()
{
    extern __shared__ float sm[];
    u64* K2p = reinterpret_cast<u64*>(sm);            // [1024][8]  64KB
    u64* V2  = reinterpret_cast<u64*>(sm + 16384);    // [2048][4]  64KB

    int bh  = blockIdx.x;
    int qt  = blockIdx.y;   // 0..1
    int tid = threadIdx.x;

    const float* gk = g_k + (size_t)bh * (Tc*DKc);
#pragma unroll
    for (int i = tid; i < 8192; i += 512) {
        int j2 = i >> 3, d = i & 7;
        K2p[i] = pack2(gk[j2*16 + d], gk[j2*16 + 8 + d]);
    }
    const ulonglong2* gv = reinterpret_cast<const ulonglong2*>(g_v + (size_t)bh * (Tc*DKc));
    ulonglong2* V4 = reinterpret_cast<ulonglong2*>(V2);
#pragma unroll
    for (int i = 0; i < 8; i++) V4[tid + 512*i] = gv[tid + 512*i];
    __syncthreads();

    int t0 = qt * 1024 + tid;
    int t1 = t0 + 512;
    const float QS = 0.35355339059327f * 1.4426950408889634f;  // 1/sqrt(8)*log2(e)
    const float* qp0 = g_q + (size_t)bh * (Tc*DKc) + t0 * DKc;
    const float* qp1 = g_q + (size_t)bh * (Tc*DKc) + t1 * DKc;
    u64 qa[8], qb[8];
#pragma unroll
    for (int d = 0; d < 8; d++) { qa[d] = dup2(qp0[d]*QS); qb[d] = dup2(qp1[d]*QS); }

    u64 la = 0, lb = 0;
    u64 aA0=0, aA1=0, aA2=0, aA3=0;
    u64 aB0=0, aB1=0, aB2=0, aB3=0;

    const ulonglong2* kp = reinterpret_cast<const ulonglong2*>(K2p);
    const ulonglong2* vp = reinterpret_cast<const ulonglong2*>(V2);

#pragma unroll 2
    for (int j2 = 0; j2 < 1024; j2++) {
        ulonglong2 kA = kp[0], kB = kp[1], kC = kp[2], kD = kp[3]; kp += 4;
        u64 sA = mul2(qa[0], kA.x);
        u64 sB = mul2(qb[0], kA.x);
        sA = fma2(qa[1], kA.y, sA);  sB = fma2(qb[1], kA.y, sB);
        sA = fma2(qa[2], kB.x, sA);  sB = fma2(qb[2], kB.x, sB);
        sA = fma2(qa[3], kB.y, sA);  sB = fma2(qb[3], kB.y, sB);
        sA = fma2(qa[4], kC.x, sA);  sB = fma2(qb[4], kC.x, sB);
        sA = fma2(qa[5], kC.y, sA);  sB = fma2(qb[5], kC.y, sB);
        sA = fma2(qa[6], kD.x, sA);  sB = fma2(qb[6], kD.x, sB);
        sA = fma2(qa[7], kD.y, sA);  sB = fma2(qb[7], kD.y, sB);
        float sa0, sa1, sb0, sb1;
        unpack2(sA, sa0, sa1);
        unpack2(sB, sb0, sb1);
        float pa0 = ex2f(sa0), pa1 = ex2f(sa1);
        float pb0 = ex2f(sb0), pb1 = ex2f(sb1);
        ulonglong2 vA = vp[0], vB = vp[1], vC = vp[2], vD = vp[3]; vp += 4;
        u64 ppa0 = dup2(pa0), ppa1 = dup2(pa1);
        u64 ppb0 = dup2(pb0), ppb1 = dup2(pb1);
        la = add2(la, pack2(pa0, pa1));
        lb = add2(lb, pack2(pb0, pb1));
        aA0 = fma2(ppa0, vA.x, aA0); aA1 = fma2(ppa0, vA.y, aA1);
        aA2 = fma2(ppa0, vB.x, aA2); aA3 = fma2(ppa0, vB.y, aA3);
        aA0 = fma2(ppa1, vC.x, aA0); aA1 = fma2(ppa1, vC.y, aA1);
        aA2 = fma2(ppa1, vD.x, aA2); aA3 = fma2(ppa1, vD.y, aA3);
        aB0 = fma2(ppb0, vA.x, aB0); aB1 = fma2(ppb0, vA.y, aB1);
        aB2 = fma2(ppb0, vB.x, aB2); aB3 = fma2(ppb0, vB.y, aB3);
        aB0 = fma2(ppb1, vC.x, aB0); aB1 = fma2(ppb1, vC.y, aB1);
        aB2 = fma2(ppb1, vD.x, aB2); aB3 = fma2(ppb1, vD.y, aB3);
    }

    int b = bh >> 3, h = bh & 7;
    {
        float llo, lhi; unpack2(la, llo, lhi);
        float inv = 1.0f / (llo + lhi);
        float o0,o1,o2,o3,o4,o5,o6,o7;
        unpack2(aA0,o0,o1); unpack2(aA1,o2,o3); unpack2(aA2,o4,o5); unpack2(aA3,o6,o7);
        float* op = g_attn + ((size_t)(b*Tc + t0)) * Ec + h * DKc;
        reinterpret_cast<float4*>(op)[0] = make_float4(o0*inv, o1*inv, o2*inv, o3*inv);
        reinterpret_cast<float4*>(op)[1] = make_float4(o4*inv, o5*inv, o6*inv, o7*inv);
    }
    {
        float llo, lhi; unpack2(lb, llo, lhi);
        float inv = 1.0f / (llo + lhi);
        float o0,o1,o2,o3,o4,o5,o6,o7;
        unpack2(aB0,o0,o1); unpack2(aB1,o2,o3); unpack2(aB2,o4,o5); unpack2(aB3,o6,o7);
        float* op = g_attn + ((size_t)(b*Tc + t1)) * Ec + h * DKc;
        reinterpret_cast<float4*>(op)[0] = make_float4(o0*inv, o1*inv, o2*inv, o3*inv);
        reinterpret_cast<float4*>(op)[1] = make_float4(o4*inv, o5*inv, o6*inv, o7*inv);
    }
}

// =====================================================================
// K3: FUSED TAIL. 64-token blocks, 128 threads, grid 256.
// oproj GEMM -> LN1 -> cos -> FFN in 4 f-chunks (W1/W2 streamed via
// smem, H chunk in smem, y held in registers) -> LN2 -> out.
// No g_x1 / g_h gmem roundtrips. smem 80,640B -> 2 CTAs/SM.
// =====================================================================
__global__ __launch_bounds__(128) void fused_tail_kernel(
    const float* __restrict__ x,
    const float* __restrict__ Wo, const float* __restrict__ bo,
    const float* __restrict__ g1, const float* __restrict__ be1,
    const float* __restrict__ W1, const float* __restrict__ b1,
    const float* __restrict__ W2, const float* __restrict__ b2,
    const float* __restrict__ g2, const float* __restrict__ be2,
    const float* __restrict__ theta_p, float* __restrict__ out)
{
    extern __shared__ float sm[];
    float* qcT   = sm;            // [64][68] 4352: attn^T for oproj, then qc^T
    float* wbuf  = sm + 4352;     // [64][68] 4352: Wo^T, then W1 chunk^T
    float* w2buf = sm + 8704;     // [64][68] 4352: W2 chunk^T [f][e]
    float* Hbuf  = sm + 13056;    // [64][68] 4352: H chunk [f][tok]
    float* sbo   = sm + 17408;    // 64
    float* sg1   = sbo + 64;
    float* sbe1  = sg1 + 64;
    float* sb2   = sbe1 + 64;
    float* sg2   = sb2 + 64;
    float* sbe2  = sg2 + 64;
    float* sb1c  = sbe2 + 64;     // 64 (b1 chunk)
    float* red1  = sb1c + 64;     // 1088
    float* red2  = red1 + 1088;   // 1088
    float* mS    = red2 + 1088;   // 64
    float* rsS   = mS + 64;       // 64
    int tid = threadIdx.x;

    // ---- Phase 1 loads: Wo^T, attn tile (e-major), biases ----
    for (int i = tid; i < 4096; i += 128) {
        int o = i >> 6, k = i & 63;
        wbuf[k*68+o] = Wo[i];
    }
    int n0 = blockIdx.x * 64;
    const float4* asrc = reinterpret_cast<const float4*>(g_attn + (size_t)n0 * Ec);
    for (int i = tid; i < 1024; i += 128) {
        int r = i >> 4, eg = i & 15;
        float4 v = asrc[i];
        qcT[(eg*4+0)*68 + r] = v.x;
        qcT[(eg*4+1)*68 + r] = v.y;
        qcT[(eg*4+2)*68 + r] = v.z;
        qcT[(eg*4+3)*68 + r] = v.w;
    }
    if (tid < 64) {
        sbo[tid] = bo[tid]; sg1[tid] = g1[tid]; sbe1[tid] = be1[tid];
        sb2[tid] = b2[tid]; sg2[tid] = g2[tid]; sbe2[tid] = be2[tid];
    }
    __syncthreads();

    int tokg = tid & 7, outg = tid >> 3;    // 8 tok-groups x 16 out-groups
    int o0 = outg * 4;

    // ---- oproj GEMM: 8 tok x 4 out per thread ----
    u64 acc[4][4];
#pragma unroll
    for (int a = 0; a < 4; a++)
#pragma unroll
        for (int j = 0; j < 4; j++) acc[a][j] = 0;
#pragma unroll 4
    for (int k = 0; k < 64; k++) {
        const ulonglong2* xr = reinterpret_cast<const ulonglong2*>(qcT + k*68 + tokg*8);
        ulonglong2 xa = xr[0], xb = xr[1];
        float4 wv = *reinterpret_cast<const float4*>(wbuf + k*68 + o0);
        u64 w0 = dup2(wv.x), w1 = dup2(wv.y), w2 = dup2(wv.z), w3 = dup2(wv.w);
        acc[0][0]=fma2(xa.x,w0,acc[0][0]); acc[0][1]=fma2(xa.x,w1,acc[0][1]);
        acc[0][2]=fma2(xa.x,w2,acc[0][2]); acc[0][3]=fma2(xa.x,w3,acc[0][3]);
        acc[1][0]=fma2(xa.y,w0,acc[1][0]); acc[1][1]=fma2(xa.y,w1,acc[1][1]);
        acc[1][2]=fma2(xa.y,w2,acc[1][2]); acc[1][3]=fma2(xa.y,w3,acc[1][3]);
        acc[2][0]=fma2(xb.x,w0,acc[2][0]); acc[2][1]=fma2(xb.x,w1,acc[2][1]);
        acc[2][2]=fma2(xb.x,w2,acc[2][2]); acc[2][3]=fma2(xb.x,w3,acc[2][3]);
        acc[3][0]=fma2(xb.y,w0,acc[3][0]); acc[3][1]=fma2(xb.y,w1,acc[3][1]);
        acc[3][2]=fma2(xb.y,w2,acc[3][2]); acc[3][3]=fma2(xb.y,w3,acc[3][3]);
    }

    float bb0 = sbo[o0+0], bb1 = sbo[o0+1], bb2 = sbo[o0+2], bb3 = sbo[o0+3];
    float y[8][4];
#pragma unroll
    for (int tp = 0; tp < 4; tp++) {
        int lt = tokg*8 + tp*2;
        float4 r0 = *reinterpret_cast<const float4*>(x + (size_t)(n0+lt)   * Ec + o0);
        float4 r1 = *reinterpret_cast<const float4*>(x + (size_t)(n0+lt+1) * Ec + o0);
        float v0,v1;
        unpack2(acc[tp][0], v0, v1); y[tp*2][0] = v0 + r0.x + bb0; y[tp*2+1][0] = v1 + r1.x + bb0;
        unpack2(acc[tp][1], v0, v1); y[tp*2][1] = v0 + r0.y + bb1; y[tp*2+1][1] = v1 + r1.y + bb1;
        unpack2(acc[tp][2], v0, v1); y[tp*2][2] = v0 + r0.z + bb2; y[tp*2+1][2] = v1 + r1.z + bb2;
        unpack2(acc[tp][3], v0, v1); y[tp*2][3] = v0 + r0.w + bb3; y[tp*2+1][3] = v1 + r1.w + bb3;
    }
    // ---- LN1 reduction ----
#pragma unroll
    for (int i = 0; i < 8; i++) {
        int lt = tokg*8 + i;
        float s1 = y[i][0]+y[i][1]+y[i][2]+y[i][3];
        float s2 = y[i][0]*y[i][0]+y[i][1]*y[i][1]+y[i][2]*y[i][2]+y[i][3]*y[i][3];
        red1[lt*17 + outg] = s1;
        red2[lt*17 + outg] = s2;
    }
    __syncthreads();
    if (tid < 64) {
        float s1 = 0.f, s2 = 0.f;
#pragma unroll
        for (int o = 0; o < 16; o++) { s1 += red1[tid*17+o]; s2 += red2[tid*17+o]; }
        float m = s1 * (1.f/64.f);
        float var = s2 * (1.f/64.f) - m*m;
        mS[tid] = m;
        rsS[tid] = rsqrtf(var + 1e-5f);
    }
    __syncthreads();

    // ---- x1 -> qc^T (overwrite qcT; oproj reads done), y := x1 + b2 ----
    float ct = __cosf(theta_p[0]);
    u64 yacc[4][4];
#pragma unroll
    for (int tp = 0; tp < 4; tp++) {
        int lt0 = tokg*8 + tp*2, lt1 = lt0 + 1;
        float m0 = mS[lt0], rs0 = rsS[lt0];
        float m1 = mS[lt1], rs1 = rsS[lt1];
#pragma unroll
        for (int j = 0; j < 4; j++) {
            int e = o0 + j;
            float x1a = (y[tp*2][j]   - m0) * rs0 * sg1[e] + sbe1[e];
            float x1b = (y[tp*2+1][j] - m1) * rs1 * sg1[e] + sbe1[e];
            qcT[e*68 + lt0] = __cosf(x1a) * ct;
            qcT[e*68 + lt1] = __cosf(x1b) * ct;
            yacc[tp][j] = pack2(x1a + sb2[e], x1b + sb2[e]);
        }
    }
    __syncthreads();

    // ---- FFN in 4 chunks of 64 f ----
#pragma unroll 1
    for (int c = 0; c < 4; c++) {
        int fbase = c * 64;
        for (int i = tid; i < 4096; i += 128) {
            int fl = i >> 6, k = i & 63;
            wbuf[k*68 + fl] = W1[(size_t)(fbase + fl)*64 + k];
        }
        for (int i = tid; i < 4096; i += 128) {
            int e = i >> 6, fl = i & 63;
            w2buf[fl*68 + e] = W2[(size_t)e*FFc + fbase + fl];
        }
        if (tid < 64) sb1c[tid] = b1[fbase + tid];
        __syncthreads();

        // ffn_h: H = relu(qc @ W1chunk^T + b1), 8 tok x 4 f per thread
        u64 facc[4][4];
#pragma unroll
        for (int a = 0; a < 4; a++)
#pragma unroll
            for (int j = 0; j < 4; j++) facc[a][j] = 0;
#pragma unroll 4
        for (int k = 0; k < 64; k++) {
            const ulonglong2* xr = reinterpret_cast<const ulonglong2*>(qcT + k*68 + tokg*8);
            ulonglong2 xa = xr[0], xb = xr[1];
            float4 wv = *reinterpret_cast<const float4*>(wbuf + k*68 + o0);
            u64 w0 = dup2(wv.x), w1 = dup2(wv.y), w2 = dup2(wv.z), w3 = dup2(wv.w);
            facc[0][0]=fma2(xa.x,w0,facc[0][0]); facc[0][1]=fma2(xa.x,w1,facc[0][1]);
            facc[0][2]=fma2(xa.x,w2,facc[0][2]); facc[0][3]=fma2(xa.x,w3,facc[0][3]);
            facc[1][0]=fma2(xa.y,w0,facc[1][0]); facc[1][1]=fma2(xa.y,w1,facc[1][1]);
            facc[1][2]=fma2(xa.y,w2,facc[1][2]); facc[1][3]=fma2(xa.y,w3,facc[1][3]);
            facc[2][0]=fma2(xb.x,w0,facc[2][0]); facc[2][1]=fma2(xb.x,w1,facc[2][1]);
            facc[2][2]=fma2(xb.x,w2,facc[2][2]); facc[2][3]=fma2(xb.x,w3,facc[2][3]);
            facc[3][0]=fma2(xb.y,w0,facc[3][0]); facc[3][1]=fma2(xb.y,w1,facc[3][1]);
            facc[3][2]=fma2(xb.y,w2,facc[3][2]); facc[3][3]=fma2(xb.y,w3,facc[3][3]);
        }
#pragma unroll
        for (int tp = 0; tp < 4; tp++) {
#pragma unroll
            for (int j = 0; j < 4; j++) {
                float lo, hi; unpack2(facc[tp][j], lo, hi);
                float bbf = sb1c[o0 + j];
                float2 hv = make_float2(fmaxf(lo + bbf, 0.f), fmaxf(hi + bbf, 0.f));
                *reinterpret_cast<float2*>(Hbuf + (o0+j)*68 + tokg*8 + tp*2) = hv;
            }
        }
        __syncthreads();

        // ffn_out accumulate: y += H^T @ W2chunk^T
#pragma unroll 4
        for (int fl = 0; fl < 64; fl++) {
            const ulonglong2* hr = reinterpret_cast<const ulonglong2*>(Hbuf + fl*68 + tokg*8);
            ulonglong2 xa = hr[0], xb = hr[1];
            float4 wv = *reinterpret_cast<const float4*>(w2buf + fl*68 + o0);
            u64 w0 = dup2(wv.x), w1 = dup2(wv.y), w2 = dup2(wv.z), w3 = dup2(wv.w);
            yacc[0][0]=fma2(xa.x,w0,yacc[0][0]); yacc[0][1]=fma2(xa.x,w1,yacc[0][1]);
            yacc[0][2]=fma2(xa.x,w2,yacc[0][2]); yacc[0][3]=fma2(xa.x,w3,yacc[0][3]);
            yacc[1][0]=fma2(xa.y,w0,yacc[1][0]); yacc[1][1]=fma2(xa.y,w1,yacc[1][1]);
            yacc[1][2]=fma2(xa.y,w2,yacc[1][2]); yacc[1][3]=fma2(xa.y,w3,yacc[1][3]);
            yacc[2][0]=fma2(xb.x,w0,yacc[2][0]); yacc[2][1]=fma2(xb.x,w1,yacc[2][1]);
            yacc[2][2]=fma2(xb.x,w2,yacc[2][2]); yacc[2][3]=fma2(xb.x,w3,yacc[2][3]);
            yacc[3][0]=fma2(xb.y,w0,yacc[3][0]); yacc[3][1]=fma2(xb.y,w1,yacc[3][1]);
            yacc[3][2]=fma2(xb.y,w2,yacc[3][2]); yacc[3][3]=fma2(xb.y,w3,yacc[3][3]);
        }
        __syncthreads();
    }

    // ---- LN2 + output ----
#pragma unroll
    for (int tp = 0; tp < 4; tp++) {
#pragma unroll
        for (int j = 0; j < 4; j++) {
            float lo, hi; unpack2(yacc[tp][j], lo, hi);
            y[tp*2][j] = lo; y[tp*2+1][j] = hi;
        }
    }
#pragma unroll
    for (int i = 0; i < 8; i++) {
        int lt = tokg*8 + i;
        float s1 = y[i][0]+y[i][1]+y[i][2]+y[i][3];
        float s2 = y[i][0]*y[i][0]+y[i][1]*y[i][1]+y[i][2]*y[i][2]+y[i][3]*y[i][3];
        red1[lt*17 + outg] = s1;
        red2[lt*17 + outg] = s2;
    }
    __syncthreads();
    if (tid < 64) {
        float s1 = 0.f, s2 = 0.f;
#pragma unroll
        for (int o = 0; o < 16; o++) { s1 += red1[tid*17+o]; s2 += red2[tid*17+o]; }
        float m = s1 * (1.f/64.f);
        float var = s2 * (1.f/64.f) - m*m;
        mS[tid] = m;
        rsS[tid] = rsqrtf(var + 1e-5f);
    }
    __syncthreads();

    float gg0 = sg2[o0+0], gg1 = sg2[o0+1], gg2v = sg2[o0+2], gg3 = sg2[o0+3];
    float ee0 = sbe2[o0+0], ee1 = sbe2[o0+1], ee2 = sbe2[o0+2], ee3 = sbe2[o0+3];
#pragma unroll
    for (int i = 0; i < 8; i++) {
        int lt = tokg*8 + i;
        float m = mS[lt], rs = rsS[lt];
        float4 v;
        v.x = (y[i][0]-m)*rs*gg0 + ee0;
        v.y = (y[i][1]-m)*rs*gg1 + ee1;
        v.z = (y[i][2]-m)*rs*gg2v + ee2;
        v.w = (y[i][3]-m)*rs*gg3 + ee3;
        *reinterpret_cast<float4*>(out + (size_t)(n0+lt) * Ec + o0) = v;
    }
}

// ---------------------------------------------------------------------------
extern "C" void kernel_launch(void* const* d_in, const int* in_sizes, int n_in,
                              void* d_out, int out_size)
{
    const float* x     = (const float*)d_in[0];
    const float* Wq    = (const float*)d_in[1];
    const float* bq    = (const float*)d_in[2];
    const float* Wk    = (const float*)d_in[3];
    const float* bk    = (const float*)d_in[4];
    const float* Wv    = (const float*)d_in[5];
    const float* bv    = (const float*)d_in[6];
    const float* Wo    = (const float*)d_in[7];
    const float* bo    = (const float*)d_in[8];
    const float* th_a  = (const float*)d_in[9];
    const float* th_f  = (const float*)d_in[10];
    const float* W1    = (const float*)d_in[11];
    const float* b1    = (const float*)d_in[12];
    const float* W2    = (const float*)d_in[13];
    const float* b2    = (const float*)d_in[14];
    const float* g1    = (const float*)d_in[15];
    const float* be1   = (const float*)d_in[16];
    const float* g2    = (const float*)d_in[17];
    const float* be2   = (const float*)d_in[18];
    float* out = (float*)d_out;

    const size_t SM1 = (8448 + 4352 + 64) * sizeof(float);     // 51,456
    const size_t SM2 = 131072;                                 // attn K+V
    const size_t SMF = (4*4352 + 7*64 + 2*1088 + 128) * sizeof(float); // 80,640

    cudaFuncSetAttribute(qkv_kernel,       cudaFuncAttributeMaxDynamicSharedMemorySize, (int)SM1);
    cudaFuncSetAttribute(attn_kernel,      cudaFuncAttributeMaxDynamicSharedMemorySize, (int)SM2);
    cudaFuncSetAttribute(fused_tail_kernel,cudaFuncAttributeMaxDynamicSharedMemorySize, (int)SMF);

    qkv_kernel<<<dim3(NTOK/128, 3), 256, SM1>>>(x, Wq, bq, Wk, bk, Wv, bv, th_a);
    attn_kernel<<<dim3(Bc*Hc, 2), 512, SM2>>>();
    fused_tail_kernel<<<NTOK/64, 128, SMF>>>(x, Wo, bo, g1, be1,
                                             W1, b1, W2, b2, g2, be2, th_f, out);
}